// round 1
// baseline (speedup 1.0000x reference)
#include <cuda_runtime.h>

// CubECLayr: Euler characteristic curve of sublevel cubical complex.
// x: (64, 3, 256, 256) f32  ->  out: (64, 96) f32  (192 images x 32 thresholds)
//
// Owner-attribution formulation: every edge/square is attributed to its max
// cell (ties broken by the reference's (a,b,c,d) ordering), so each pixel
// contributes a single signed weight w to the histogram at its own bin.

#define NBINS 33
#define TPB   256

__device__ __forceinline__ float ldpad(const float* __restrict__ base, int r, int c) {
    if ((unsigned)r < 256u && (unsigned)c < 256u)
        return __ldg(base + r * 256 + c);
    return __int_as_float(0x7f800000);  // +INF: removes nonexistent cells
}

__global__ void ecc_zero(float* __restrict__ out) {
    int i = blockIdx.x * blockDim.x + threadIdx.x;
    if (i < 192 * 32) out[i] = 0.0f;
}

__global__ __launch_bounds__(TPB) void ecc_main(const float* __restrict__ x,
                                                float* __restrict__ out) {
    __shared__ int sh[TPB * NBINS];   // per-thread private histograms
    __shared__ int red[NBINS];        // block-reduced histogram

    const int tid  = threadIdx.x;
    const int img  = blockIdx.x >> 2;   // 192 images
    const int band = blockIdx.x & 3;    // 4 bands of 64 rows
    const int r0   = band * 64;
    const int c    = tid;               // one column per thread
    const int lane = tid & 31;
    const float* __restrict__ base = x + (size_t)img * 65536;

    int* h = &sh[tid * NBINS];
#pragma unroll
    for (int b = 0; b < NBINS; b++) h[b] = 0;

    const float FINF = __int_as_float(0x7f800000);

    // Rolling 3-row window: up (r-1), cur (r), down (r+1) with left/right shifts.
    float vU = (r0 > 0) ? __ldg(base + (r0 - 1) * 256 + c) : FINF;
    float vC = __ldg(base + r0 * 256 + c);
    float uL = __shfl_up_sync(0xffffffffu, vU, 1);
    float uR = __shfl_down_sync(0xffffffffu, vU, 1);
    float cL = __shfl_up_sync(0xffffffffu, vC, 1);
    float cR = __shfl_down_sync(0xffffffffu, vC, 1);
    if (lane == 0)  { uL = ldpad(base, r0 - 1, c - 1); cL = ldpad(base, r0, c - 1); }
    if (lane == 31) { uR = ldpad(base, r0 - 1, c + 1); cR = ldpad(base, r0, c + 1); }

#pragma unroll 4
    for (int r = r0; r < r0 + 64; ++r) {
        const int rn = r + 1;
        float vD = (rn < 256) ? __ldg(base + rn * 256 + c) : FINF;
        float dL = __shfl_up_sync(0xffffffffu, vD, 1);
        float dR = __shfl_down_sync(0xffffffffu, vD, 1);
        if (lane == 0)  dL = ldpad(base, rn, c - 1);
        if (lane == 31) dR = ldpad(base, rn, c + 1);

        const float m = vC;
        // 8 neighbor comparisons; strict '>' against earlier-ordered cells,
        // '>=' against later-ordered cells (matches reference tie-breaking).
        const int gl   = m > cL;
        const int ger  = m >= cR;
        const int gu   = m > vU;
        const int ged  = m >= vD;
        const int gul  = m > uL;
        const int gur  = m > uR;
        const int gedl = m >= dL;
        const int gedr = m >= dR;

        int w = 1 - gl - ger - gu - ged                // vertex − owned edges
              + (gl & gu & gul)                         // square up-left (pos d)
              + (gu & gur & ger)                        // square up-right (pos c)
              + (gl & gedl & ged)                       // square down-left (pos b)
              + (ger & ged & gedr);                     // square down-right (pos a)

        int k = __float2int_ru(m * 31.0f);              // bin = ceil(f/DT), DT = 1/31
        k = max(0, min(k, 32));
        h[k] += w;

        vU = vC; uL = cL; uR = cR;                      // roll window
        vC = vD; cL = dL; cR = dR;
    }

    __syncthreads();

    // Reduce 256 private histograms -> 33 bins (conflict-free: stride 33 ints).
    if (tid < NBINS) {
        int s = 0;
#pragma unroll 8
        for (int j = 0; j < TPB; ++j) s += sh[j * NBINS + tid];
        red[tid] = s;
    }
    __syncthreads();

    // Partial cumsum of this band; bands combine linearly via exact
    // integer-valued float atomics (deterministic).
    if (tid < 32) {
        int s = 0;
        for (int kk = 0; kk <= tid; ++kk) s += red[kk];
        atomicAdd(&out[img * 32 + tid], (float)s);
    }
}

extern "C" void kernel_launch(void* const* d_in, const int* in_sizes, int n_in,
                              void* d_out, int out_size) {
    const float* x = (const float*)d_in[0];
    float* out = (float*)d_out;
    ecc_zero<<<24, 256>>>(out);
    ecc_main<<<768, 256>>>(x, out);
}

// round 2
// speedup vs baseline: 1.3101x; 1.3101x over previous
#include <cuda_runtime.h>

// CubECLayr: Euler characteristic curve of sublevel cubical complex.
// x: (64,3,256,256) f32 -> out: (192,32) f32.
//
// Owner attribution: each edge/square is counted at its max cell (reference
// tie-order), giving one signed weight per pixel. Pairwise compares are shared
// between the two incident pixels via complementary strictness:
//   a >= b  <=>  !(b > a)     (no NaNs in data)
// so only 4 unique compares/pixel: horizontal, vertical, diag, anti-diag.

#define TPB   128
#define RPW   16          // rows per warp
#define NB    32          // bins 0..31 (data in [0,1) => bin <= 31)

__global__ void ecc_zero(float* __restrict__ out) {
    int i = blockIdx.x * blockDim.x + threadIdx.x;
    if (i < 192 * 32) out[i] = 0.0f;
}

__global__ __launch_bounds__(TPB) void ecc_main(const float* __restrict__ x,
                                                float* __restrict__ out) {
    __shared__ int sh[NB * TPB];   // h[k][tid], stride 128 -> bank = tid%32 (conflict-free)
    __shared__ int red[NB];

    const int tid  = threadIdx.x;
    const int lane = tid & 31;
    const int wid  = tid >> 5;
    const int img  = blockIdx.x >> 2;
    const int band = blockIdx.x & 3;
    const int R0   = band * 64 + wid * RPW;      // this warp's first row
    const float* __restrict__ base = x + (size_t)img * 65536 + lane * 8;

#pragma unroll
    for (int k = 0; k < NB; ++k) sh[(k << 7) + tid] = 0;

    const float FINF = __int_as_float(0x7f800000);
    const unsigned FULL = 0xffffffffu;

    float cur[8], nxt[8];
    float curL, curR;
    int pvp[8], pdp[8], pap[8], pdpm1, pap8;     // carried up-row predicates

    // ---- load row R0 ----
    {
        float4 a = *(const float4*)(base + R0 * 256);
        float4 b = *(const float4*)(base + R0 * 256 + 4);
        cur[0]=a.x; cur[1]=a.y; cur[2]=a.z; cur[3]=a.w;
        cur[4]=b.x; cur[5]=b.y; cur[6]=b.z; cur[7]=b.w;
    }
    curL = __shfl_up_sync(FULL, cur[7], 1);  if (lane == 0)  curL = FINF;
    curR = __shfl_down_sync(FULL, cur[0], 1); if (lane == 31) curR = FINF;

    // ---- carried predicates from row R0-1 -> R0 ----
    if (R0 == 0) {
#pragma unroll
        for (int c = 0; c < 8; ++c) { pvp[c] = 0; pdp[c] = 0; pap[c] = 0; }
        pdpm1 = 0; pap8 = 0;
    } else {
        float p[8], pL, pR;
        float4 a = *(const float4*)(base + (R0 - 1) * 256);
        float4 b = *(const float4*)(base + (R0 - 1) * 256 + 4);
        p[0]=a.x; p[1]=a.y; p[2]=a.z; p[3]=a.w;
        p[4]=b.x; p[5]=b.y; p[6]=b.z; p[7]=b.w;
        pL = __shfl_up_sync(FULL, p[7], 1);  if (lane == 0)  pL = FINF;
        pR = __shfl_down_sync(FULL, p[0], 1); if (lane == 31) pR = FINF;
#pragma unroll
        for (int c = 0; c < 8; ++c) {
            float cr = (c < 7) ? cur[c + 1] : curR;
            float cl = (c > 0) ? cur[c - 1] : curL;
            pvp[c] = cur[c] > p[c];   // gu(R0,c)
            pdp[c] = cr     > p[c];   // gul(R0,c+1)
            pap[c] = cl     > p[c];   // gur(R0,c-1)
        }
        pdpm1 = cur[0] > pL;          // gul(R0, c=0)
        pap8  = cur[7] > pR;          // gur(R0, c=7)
    }

    // ---- preload row R0+1 (always < 256) ----
    {
        float4 a = *(const float4*)(base + (R0 + 1) * 256);
        float4 b = *(const float4*)(base + (R0 + 1) * 256 + 4);
        nxt[0]=a.x; nxt[1]=a.y; nxt[2]=a.z; nxt[3]=a.w;
        nxt[4]=b.x; nxt[5]=b.y; nxt[6]=b.z; nxt[7]=b.w;
    }

    // ---- main loop over rows ----
    for (int r = R0; r < R0 + RPW; ++r) {
        // promote nxt -> dn (shuffles consume the loads issued last iteration)
        float dnL = __shfl_up_sync(FULL, nxt[7], 1);  if (lane == 0)  dnL = FINF;
        float dnR = __shfl_down_sync(FULL, nxt[0], 1); if (lane == 31) dnR = FINF;
        float dn[8];
#pragma unroll
        for (int c = 0; c < 8; ++c) dn[c] = nxt[c];

        // prefetch row r+2 (only rows we actually need; else +INF)
        {
            int rp = r + 2;
            if (rp <= R0 + RPW && rp < 256) {
                float4 a = *(const float4*)(base + rp * 256);
                float4 b = *(const float4*)(base + rp * 256 + 4);
                nxt[0]=a.x; nxt[1]=a.y; nxt[2]=a.z; nxt[3]=a.w;
                nxt[4]=b.x; nxt[5]=b.y; nxt[6]=b.z; nxt[7]=b.w;
            } else {
#pragma unroll
                for (int c = 0; c < 8; ++c) nxt[c] = FINF;
            }
        }

        // horizontal predicates for the current row
        int phm1 = cur[0] > curL;              // gl at c=0
        int ph[8];
#pragma unroll
        for (int c = 0; c < 8; ++c)
            ph[c] = ((c < 7) ? cur[c + 1] : curR) > cur[c];

        int pd_pending = 0;                    // delayed pdp writeback
#pragma unroll
        for (int c = 0; c < 8; ++c) {
            const float m = cur[c];
            const int pv = dn[c] > m;                              // !ged
            const int pd = (((c < 7) ? dn[c + 1] : dnR) > m);      // !gedr
            const int pa = (((c > 0) ? dn[c - 1] : dnL) > m);      // !gedl

            const int gl   = (c > 0) ? ph[c - 1] : phm1;
            const int ger  = ph[c] ^ 1;
            const int gu   = pvp[c];
            const int ged  = pv ^ 1;
            const int gul  = (c > 0) ? pdp[c - 1] : pdpm1;
            const int gur  = (c < 7) ? pap[c + 1] : pap8;
            const int gedl = pa ^ 1;
            const int gedr = pd ^ 1;

            int w = 1 - gl - ger - gu - ged
                  + (gl  & gu  & gul)
                  + (gu  & ger & gur)
                  + (gl  & ged & gedl)
                  + (ger & ged & gedr);

            int k = __float2int_ru(m * 31.0f);   // ceil(f/DT), DT=1/31
            k = min(k, 31);                      // safety clamp only
            sh[(k << 7) + tid] += w;

            // carried-pred updates (read-before-write ordering preserved)
            pvp[c] = pv;
            if (c > 0) pdp[c - 1] = pd_pending;
            pd_pending = pd;
            pap[c] = pa;
        }
        pdp[7] = pd_pending;
        pdpm1 = dn[0] > curL;
        pap8  = dn[7] > curR;

        // roll window
#pragma unroll
        for (int c = 0; c < 8; ++c) cur[c] = dn[c];
        curL = dnL; curR = dnR;
    }

    __syncthreads();

    // ---- block reduction: 128 threads, 4 partials per bin, lane-rotated (conflict-free)
    {
        const int b = tid >> 2, g = tid & 3;
        int s = 0;
#pragma unroll
        for (int j = 0; j < 32; ++j)
            s += sh[(b << 7) + (g << 5) + ((j + tid) & 31)];
        s += __shfl_xor_sync(FULL, s, 1);
        s += __shfl_xor_sync(FULL, s, 2);
        if (g == 0) red[b] = s;
    }
    __syncthreads();

    // ---- inclusive cumsum + exact integer-float atomic combine across bands
    if (tid < 32) {
        int acc = 0;
        for (int k = 0; k <= tid; ++k) acc += red[k];   // broadcast reads
        atomicAdd(&out[img * 32 + tid], (float)acc);
    }
}

extern "C" void kernel_launch(void* const* d_in, const int* in_sizes, int n_in,
                              void* d_out, int out_size) {
    const float* x = (const float*)d_in[0];
    float* out = (float*)d_out;
    ecc_zero<<<24, 256>>>(out);
    ecc_main<<<768, TPB>>>(x, out);
}

// round 3
// speedup vs baseline: 1.5452x; 1.1794x over previous
#include <cuda_runtime.h>

// CubECLayr: Euler characteristic curve of sublevel cubical complex.
// x: (64,3,256,256) f32 -> out: (192,32) f32.
//
// Owner attribution: each edge/square counted at its max cell (reference tie
// order) -> one signed weight per pixel. All comparisons are computed as
// {0,-1} sign masks:  (a > b)  <=>  __float_as_int(b - a) >> 31   (no NaNs),
// which puts the subtract on the FMA pipe and makes each square test a single
// 3-input LOP3. Compares are shared between incident pixels via
// complementary strictness (a >= b <=> !(b > a)).

#define TPB 128
#define RPW 8
#define NB  32          // data in [0,1) => bins 0..31 only

// mask = -1 iff a > b, else 0 (a,b never NaN; exact for +-0, subnormals, INF)
__device__ __forceinline__ int MGT(float a, float b) {
    return __float_as_int(b - a) >> 31;
}

__global__ void ecc_zero(float* __restrict__ out) {
    int i = blockIdx.x * blockDim.x + threadIdx.x;
    if (i < 192 * 32) out[i] = 0.0f;
}

__global__ __launch_bounds__(TPB) void ecc_main(const float* __restrict__ x,
                                                float* __restrict__ out) {
    __shared__ int sh[NB * TPB];   // h[k][tid], stride 128 -> conflict-free
    __shared__ int red[NB];

    const int tid  = threadIdx.x;
    const int lane = tid & 31;
    const int wid  = tid >> 5;
    const int img  = blockIdx.x >> 3;     // 192 images
    const int band = blockIdx.x & 7;      // 8 bands of 32 rows
    const int R0   = band * 32 + wid * RPW;
    const float* __restrict__ base = x + (size_t)img * 65536 + lane * 8;

#pragma unroll
    for (int k = 0; k < NB; ++k) sh[(k << 7) + tid] = 0;

    const float FINF = __int_as_float(0x7f800000);
    const unsigned FULL = 0xffffffffu;

    float cur[8], nxt[8], curR;
    int h[8], hm1;                 // horizontal masks for cur row
    int P[8], D[8], A[8];          // carried up-row masks (v, diag, anti-diag)
    int pdm1, pa8;

    // ---- load row R0, horizontal masks ----
    {
        float4 a4 = *(const float4*)(base + R0 * 256);
        float4 b4 = *(const float4*)(base + R0 * 256 + 4);
        cur[0]=a4.x; cur[1]=a4.y; cur[2]=a4.z; cur[3]=a4.w;
        cur[4]=b4.x; cur[5]=b4.y; cur[6]=b4.z; cur[7]=b4.w;
    }
    curR = __shfl_down_sync(FULL, cur[0], 1); if (lane == 31) curR = FINF;
#pragma unroll
    for (int c = 0; c < 8; ++c) h[c] = MGT((c < 7) ? cur[c + 1] : curR, cur[c]);
    hm1 = __shfl_up_sync(FULL, h[7], 1); if (lane == 0) hm1 = 0;

    // ---- carried masks from row R0-1 ----
    if (R0 > 0) {
        float pr[8];
        float4 a4 = *(const float4*)(base + (R0 - 1) * 256);
        float4 b4 = *(const float4*)(base + (R0 - 1) * 256 + 4);
        pr[0]=a4.x; pr[1]=a4.y; pr[2]=a4.z; pr[3]=a4.w;
        pr[4]=b4.x; pr[5]=b4.y; pr[6]=b4.z; pr[7]=b4.w;
        float prL = __shfl_up_sync(FULL, pr[7], 1);  if (lane == 0)  prL = FINF;
        float prR = __shfl_down_sync(FULL, pr[0], 1); if (lane == 31) prR = FINF;
#pragma unroll
        for (int c = 0; c < 8; ++c) {
            P[c] = MGT(cur[c], pr[c]);
            D[c] = MGT((c < 7) ? cur[c + 1] : curR, pr[c]);
            A[c] = (c > 0) ? MGT(cur[c - 1], pr[c]) : 0;
        }
        pdm1 = MGT(cur[0], prL);   // INF pad -> 0 automatically
        pa8  = MGT(cur[7], prR);
    } else {
#pragma unroll
        for (int c = 0; c < 8; ++c) { P[c] = 0; D[c] = 0; A[c] = 0; }
        pdm1 = 0; pa8 = 0;
    }

    // ---- preload row R0+1 (always < 256) ----
    {
        float4 a4 = *(const float4*)(base + (R0 + 1) * 256);
        float4 b4 = *(const float4*)(base + (R0 + 1) * 256 + 4);
        nxt[0]=a4.x; nxt[1]=a4.y; nxt[2]=a4.z; nxt[3]=a4.w;
        nxt[4]=b4.x; nxt[5]=b4.y; nxt[6]=b4.z; nxt[7]=b4.w;
    }

    // ---- main loop ----
    for (int r = R0; r < R0 + RPW; ++r) {
        float dn[8];
#pragma unroll
        for (int c = 0; c < 8; ++c) dn[c] = nxt[c];
        float dnL = __shfl_up_sync(FULL, dn[7], 1);  if (lane == 0)  dnL = FINF;
        float dnR = __shfl_down_sync(FULL, dn[0], 1); if (lane == 31) dnR = FINF;

        // prefetch row r+2
        {
            int rp = r + 2;
            if (rp <= R0 + RPW && rp < 256) {
                float4 a4 = *(const float4*)(base + rp * 256);
                float4 b4 = *(const float4*)(base + rp * 256 + 4);
                nxt[0]=a4.x; nxt[1]=a4.y; nxt[2]=a4.z; nxt[3]=a4.w;
                nxt[4]=b4.x; nxt[5]=b4.y; nxt[6]=b4.z; nxt[7]=b4.w;
            } else {
#pragma unroll
                for (int c = 0; c < 8; ++c) nxt[c] = FINF;
            }
        }

        int pend = 0;   // delayed D writeback
#pragma unroll
        for (int c = 0; c < 8; ++c) {
            const float m = cur[c];
            const int v = MGT(dn[c], m);                          // dn > m
            const int d = MGT((c < 7) ? dn[c + 1] : dnR, m);      // dn-right > m
            const int a = MGT((c > 0) ? dn[c - 1] : dnL, m);      // dn-left  > m

            const int gl  = (c > 0) ? h[c - 1] : hm1;   // m >  left
            const int nh  = h[c];                        // right > m  (ger = ~nh)
            const int gu  = P[c];                        // m >  up
            const int gul = (c > 0) ? D[c - 1] : pdm1;   // m >  up-left
            const int gur = (c < 7) ? A[c + 1] : pa8;    // m >  up-right

            const int s1 = gl &  gu & gul;               // square up-left
            const int s2 = gu & ~nh & gur;               // square up-right
            const int s3 = gl & ~v  & ~a;                // square down-left
            const int s4 = ~nh & ~v & ~d;                // square down-right

            const int w = (gl - nh) + (gu - v) - ((s1 + s2) + (s3 + s4)) - 1;

            int k = __float2int_ru(m * 31.0f);           // ceil(f/DT), DT=1/31
            k = min(k, 31);
            sh[(k << 7) + tid] += w;

            P[c] = v;
            if (c > 0) D[c - 1] = pend;
            pend = d;
            A[c] = a;
        }
        D[7] = pend;
        pdm1 = __shfl_up_sync(FULL, D[7], 1);  if (lane == 0)  pdm1 = 0;
        pa8  = __shfl_down_sync(FULL, A[0], 1); if (lane == 31) pa8 = 0;

        // roll window + fresh horizontal masks
#pragma unroll
        for (int c = 0; c < 8; ++c) cur[c] = dn[c];
        curR = dnR;
#pragma unroll
        for (int c = 0; c < 8; ++c) h[c] = MGT((c < 7) ? cur[c + 1] : curR, cur[c]);
        hm1 = __shfl_up_sync(FULL, h[7], 1); if (lane == 0) hm1 = 0;
    }

    __syncthreads();

    // ---- block reduction: 4 partial-groups per bin, lane-rotated (conflict-free)
    {
        const int b = tid >> 2, g = tid & 3;
        int s = 0;
#pragma unroll
        for (int j = 0; j < 32; ++j)
            s += sh[(b << 7) + (g << 5) + ((j + tid) & 31)];
        s += __shfl_xor_sync(FULL, s, 1);
        s += __shfl_xor_sync(FULL, s, 2);
        if (g == 0) red[b] = s;
    }
    __syncthreads();

    // ---- inclusive cumsum + exact integer-float atomic combine across bands
    if (tid < 32) {
        int acc = 0;
        for (int k = 0; k <= tid; ++k) acc += red[k];
        atomicAdd(&out[img * 32 + tid], (float)acc);
    }
}

extern "C" void kernel_launch(void* const* d_in, const int* in_sizes, int n_in,
                              void* d_out, int out_size) {
    const float* x = (const float*)d_in[0];
    float* out = (float*)d_out;
    ecc_zero<<<24, 256>>>(out);
    ecc_main<<<1536, TPB>>>(x, out);
}